// round 15
// baseline (speedup 1.0000x reference)
#include <cuda_runtime.h>
#include <math.h>

// Fully-fused Sherman–Morrison delta-rule update (single launch).
// out[b,o,:] = W[b,o,:] - scale_b * (W[b,o,:]·x_b - g[b,o]) * x_b
// scale_b = 1/(1024 + softplus(x_b·eta_w + eta_b))
//
// FINAL converged configuration (14 rounds of measurement):
//  - 256-thread blocks, one warp per output row, grid 16384
//  - interleaved float4 W-load + dot FMA (MLP=8): beats front-batched loads,
//    wider blocks, multi-row warps, in-loop eta fusion, and __ldcs reads
//  - eta partials -> red[]; single barrier AFTER the W loop; per-warp scale
//    finish (3 shfls + redundant softplus — no t0 serialization)
//  - plain W loads; __stcs on the write-once output stream
// Measured at the mixed-stream HBM3e roofline: ~6.7-6.8 TB/s sustained on a
// 1.074 GB traffic floor.
__global__ __launch_bounds__(256) void sm_update_fused_kernel(
    const float* __restrict__ W,
    const float* __restrict__ x,
    const float* __restrict__ grad,
    const float* __restrict__ eta_w,
    const float* __restrict__ eta_b,
    float* __restrict__ out) {

    __shared__ float4 xs[256];   // x_b: 1024 floats
    __shared__ float red[8];

    const int b = blockIdx.x >> 7;        // 128 blocks per batch
    const int ochunk = blockIdx.x & 127;
    const int t = threadIdx.x;
    const int warp = t >> 5;
    const int lane = t & 31;

    const float ebias = eta_b[0];

    // stage x_b
    xs[t] = reinterpret_cast<const float4*>(x + (size_t)b * 1024)[t];
    __syncthreads();

    // eta partial: dot(x_b, eta_w), 4 elems/thread (4KB, L2-resident)
    {
        const float4 ew = reinterpret_cast<const float4*>(eta_w)[t];
        const float4 xv = xs[t];
        float p = xv.x * ew.x + xv.y * ew.y + xv.z * ew.z + xv.w * ew.w;
        for (int off = 16; off; off >>= 1)
            p += __shfl_xor_sync(0xffffffffu, p, off);
        if (lane == 0) red[warp] = p;
    }

    // W row: interleaved load + FMA (long-latency phase; overlaps reduction)
    const int o = (ochunk << 3) + warp;
    const size_t row_off = ((size_t)b * 1024 + o) * 1024;
    const float4* wrow = reinterpret_cast<const float4*>(W + row_off);

    const float g = grad[(size_t)b * 1024 + o];

    float4 wv[8];
    float dot = 0.0f;
#pragma unroll
    for (int k = 0; k < 8; k++) {
        const int idx = (k << 5) + lane;
        wv[k] = wrow[idx];
        const float4 xv = xs[idx];
        dot += wv[k].x * xv.x + wv[k].y * xv.y + wv[k].z * xv.z + wv[k].w * xv.w;
    }
    for (int off = 16; off; off >>= 1)
        dot += __shfl_xor_sync(0xffffffffu, dot, off);

    // per-warp scale finish
    __syncthreads();               // red[] complete (only remaining barrier)
    float s = red[lane & 7];
    s += __shfl_xor_sync(0xffffffffu, s, 4);
    s += __shfl_xor_sync(0xffffffffu, s, 2);
    s += __shfl_xor_sync(0xffffffffu, s, 1);
    const float z = s + ebias;
    const float sp = fmaxf(z, 0.0f) + log1pf(expf(-fabsf(z)));
    const float scale = 1.0f / (1024.0f + sp);

    const float se = scale * (dot - g);

    float4* orow = reinterpret_cast<float4*>(out + row_off);
#pragma unroll
    for (int k = 0; k < 8; k++) {
        const int idx = (k << 5) + lane;
        const float4 xv = xs[idx];
        float4 r;
        r.x = wv[k].x - se * xv.x;
        r.y = wv[k].y - se * xv.y;
        r.z = wv[k].z - se * xv.z;
        r.w = wv[k].w - se * xv.w;
        __stcs(orow + idx, r);     // write-once output: streaming store
    }
}

extern "C" void kernel_launch(void* const* d_in, const int* in_sizes, int n_in,
                              void* d_out, int out_size) {
    // metadata order: W_t [128,1024,1024], x_t [128,1024], grad_l_in [128,1024],
    //                 eta_w [1,1024], eta_b [1]
    const float* W     = (const float*)d_in[0];
    const float* x     = (const float*)d_in[1];
    const float* grad  = (const float*)d_in[2];
    const float* eta_w = (const float*)d_in[3];
    const float* eta_b = (const float*)d_in[4];
    float* out = (float*)d_out;

    sm_update_fused_kernel<<<128 * 128, 256>>>(W, x, grad, eta_w, eta_b, out);
}

// round 16
// speedup vs baseline: 1.0041x; 1.0041x over previous
#include <cuda_runtime.h>
#include <math.h>

// Fully-fused Sherman–Morrison delta-rule update (single launch).
// out[b,o,:] = W[b,o,:] - scale_b * (W[b,o,:]·x_b - g[b,o]) * x_b
// scale_b = 1/(1024 + softplus(x_b·eta_w + eta_b))
//
// Converged configuration (15 rounds of measurement); this round tests the
// last unmeasured cell in the store-hint matrix: __stwt (write-through) on
// the write-once output stream. Everything else is the proven-best body:
//  - 256-thread blocks, one warp per output row, grid 16384
//  - interleaved float4 W-load + dot FMA (MLP=8), plain loads
//  - eta partials -> red[]; single barrier AFTER the W loop; per-warp
//    scale finish (3 shfls + redundant softplus)
__global__ __launch_bounds__(256) void sm_update_fused_kernel(
    const float* __restrict__ W,
    const float* __restrict__ x,
    const float* __restrict__ grad,
    const float* __restrict__ eta_w,
    const float* __restrict__ eta_b,
    float* __restrict__ out) {

    __shared__ float4 xs[256];   // x_b: 1024 floats
    __shared__ float red[8];

    const int b = blockIdx.x >> 7;        // 128 blocks per batch
    const int ochunk = blockIdx.x & 127;
    const int t = threadIdx.x;
    const int warp = t >> 5;
    const int lane = t & 31;

    const float ebias = eta_b[0];

    // stage x_b
    xs[t] = reinterpret_cast<const float4*>(x + (size_t)b * 1024)[t];
    __syncthreads();

    // eta partial: dot(x_b, eta_w), 4 elems/thread (4KB, L2-resident)
    {
        const float4 ew = reinterpret_cast<const float4*>(eta_w)[t];
        const float4 xv = xs[t];
        float p = xv.x * ew.x + xv.y * ew.y + xv.z * ew.z + xv.w * ew.w;
        for (int off = 16; off; off >>= 1)
            p += __shfl_xor_sync(0xffffffffu, p, off);
        if (lane == 0) red[warp] = p;
    }

    // W row: interleaved load + FMA (long-latency phase; overlaps reduction)
    const int o = (ochunk << 3) + warp;
    const size_t row_off = ((size_t)b * 1024 + o) * 1024;
    const float4* wrow = reinterpret_cast<const float4*>(W + row_off);

    const float g = grad[(size_t)b * 1024 + o];

    float4 wv[8];
    float dot = 0.0f;
#pragma unroll
    for (int k = 0; k < 8; k++) {
        const int idx = (k << 5) + lane;
        wv[k] = wrow[idx];
        const float4 xv = xs[idx];
        dot += wv[k].x * xv.x + wv[k].y * xv.y + wv[k].z * xv.z + wv[k].w * xv.w;
    }
    for (int off = 16; off; off >>= 1)
        dot += __shfl_xor_sync(0xffffffffu, dot, off);

    // per-warp scale finish
    __syncthreads();               // red[] complete (only remaining barrier)
    float s = red[lane & 7];
    s += __shfl_xor_sync(0xffffffffu, s, 4);
    s += __shfl_xor_sync(0xffffffffu, s, 2);
    s += __shfl_xor_sync(0xffffffffu, s, 1);
    const float z = s + ebias;
    const float sp = fmaxf(z, 0.0f) + log1pf(expf(-fabsf(z)));
    const float scale = 1.0f / (1024.0f + sp);

    const float se = scale * (dot - g);

    float4* orow = reinterpret_cast<float4*>(out + row_off);
#pragma unroll
    for (int k = 0; k < 8; k++) {
        const int idx = (k << 5) + lane;
        const float4 xv = xs[idx];
        float4 r;
        r.x = wv[k].x - se * xv.x;
        r.y = wv[k].y - se * xv.y;
        r.z = wv[k].z - se * xv.z;
        r.w = wv[k].w - se * xv.w;
        __stwt(orow + idx, r);     // write-through: skip L2 write-allocate
    }
}

extern "C" void kernel_launch(void* const* d_in, const int* in_sizes, int n_in,
                              void* d_out, int out_size) {
    // metadata order: W_t [128,1024,1024], x_t [128,1024], grad_l_in [128,1024],
    //                 eta_w [1,1024], eta_b [1]
    const float* W     = (const float*)d_in[0];
    const float* x     = (const float*)d_in[1];
    const float* grad  = (const float*)d_in[2];
    const float* eta_w = (const float*)d_in[3];
    const float* eta_b = (const float*)d_in[4];
    float* out = (float*)d_out;

    sm_update_fused_kernel<<<128 * 128, 256>>>(W, x, grad, eta_w, eta_b, out);
}